// round 15
// baseline (speedup 1.0000x reference)
#include <cuda_runtime.h>
#include <cuda_fp16.h>
#include <math.h>
#include <stdint.h>

// ---------------------------------------------------------------------------
// Problem constants
// ---------------------------------------------------------------------------
#define BB 4
#define TT 2048
#define DD 1024
#define HH 16
#define HD 64
#define FF 4096
#define MM (BB * TT)       // 8192 rows
#define EPS 1e-5f

// ---------------------------------------------------------------------------
// Scratch (allocation-free: __device__ globals)
// ---------------------------------------------------------------------------
__device__ __half g_h   [(size_t)MM * DD];      // LN1 out (fp16)
__device__ __half g_qkv [(size_t)MM * 3 * DD];  // QKV out (fp16)
__device__ __half g_attn[(size_t)MM * DD];      // attention out (fp16)
__device__ float  g_x2  [(size_t)MM * DD];      // residual stream 2 (fp32)
__device__ __half g_h2  [(size_t)MM * DD];      // LN2 out (fp16)
__device__ __half g_ff1 [(size_t)MM * FF];      // FFN1 out (fp16)
// fp16 weights, transposed to [N][K]
__device__ __half g_wqkv[(size_t)(3 * DD) * DD];
__device__ __half g_wo  [(size_t)DD * DD];
__device__ __half g_w1  [(size_t)FF * DD];
__device__ __half g_w2  [(size_t)DD * FF];

// ---------------------------------------------------------------------------
// helpers
// ---------------------------------------------------------------------------
__device__ __forceinline__ void mma_f16(float c[4], const uint32_t a[4],
                                        const uint32_t b[2]) {
    asm volatile(
        "mma.sync.aligned.m16n8k16.row.col.f32.f16.f16.f32 "
        "{%0,%1,%2,%3}, {%4,%5,%6,%7}, {%8,%9}, {%0,%1,%2,%3};"
        : "+f"(c[0]), "+f"(c[1]), "+f"(c[2]), "+f"(c[3])
        : "r"(a[0]), "r"(a[1]), "r"(a[2]), "r"(a[3]), "r"(b[0]), "r"(b[1]));
}
__device__ __forceinline__ void ldsm_x4(uint32_t r[4], uint32_t saddr) {
    asm volatile("ldmatrix.sync.aligned.m8n8.x4.shared.b16 {%0,%1,%2,%3}, [%4];"
        : "=r"(r[0]), "=r"(r[1]), "=r"(r[2]), "=r"(r[3]) : "r"(saddr));
}
__device__ __forceinline__ void ldsm_x4_t(uint32_t r[4], uint32_t saddr) {
    asm volatile("ldmatrix.sync.aligned.m8n8.x4.trans.shared.b16 {%0,%1,%2,%3}, [%4];"
        : "=r"(r[0]), "=r"(r[1]), "=r"(r[2]), "=r"(r[3]) : "r"(saddr));
}
__device__ __forceinline__ void cp_async16(uint32_t saddr, const void* gptr) {
    asm volatile("cp.async.cg.shared.global [%0], [%1], 16;"
                 :: "r"(saddr), "l"(gptr) : "memory");
}
__device__ __forceinline__ void cp_commit() {
    asm volatile("cp.async.commit_group;" ::: "memory");
}
template <int N>
__device__ __forceinline__ void cp_wait() {
    asm volatile("cp.async.wait_group %0;" :: "n"(N) : "memory");
}
__device__ __forceinline__ uint32_t smem_u32(const void* p) {
    uint32_t a;
    asm("{ .reg .u64 t; cvta.to.shared.u64 t, %1; cvt.u32.u64 %0, t; }"
        : "=r"(a) : "l"(p));
    return a;
}
__device__ __forceinline__ uint32_t pack_h2(float a, float b) {
    __half2 h = __floats2half2_rn(a, b);
    return *(uint32_t*)&h;
}

// ---------------------------------------------------------------------------
// Weight preprocessing: all 6 transposes ([R][C] fp32 -> [C][R] fp16) fused
// into one launch.
// ---------------------------------------------------------------------------
__global__ __launch_bounds__(256) void transpose_all_kernel(
    const float* __restrict__ Wq, const float* __restrict__ Wk,
    const float* __restrict__ Wv, const float* __restrict__ Wo,
    const float* __restrict__ W1, const float* __restrict__ W2,
    __half* __restrict__ wqkv, __half* __restrict__ wo,
    __half* __restrict__ w1, __half* __restrict__ w2)
{
    const int id = blockIdx.x;
    const float* in;
    __half* out;
    int R, C, bx, by;
    if (id < 4096) {
        const int w = id >> 10, t = id & 1023;
        bx = t & 31; by = t >> 5;
        R = DD; C = DD;
        if (w == 0)      { in = Wq; out = wqkv; }
        else if (w == 1) { in = Wk; out = wqkv + (size_t)DD * DD; }
        else if (w == 2) { in = Wv; out = wqkv + (size_t)2 * DD * DD; }
        else             { in = Wo; out = wo; }
    } else if (id < 8192) {
        const int t = id - 4096;
        bx = t & 127; by = t >> 7;
        in = W1; out = w1; R = DD; C = FF;
    } else {
        const int t = id - 8192;
        bx = t & 31; by = t >> 5;
        in = W2; out = w2; R = FF; C = DD;
    }

    __shared__ float tl[32][33];
    const int c0 = bx * 32;
    const int r0 = by * 32;
    const int tx = threadIdx.x & 31, ty = threadIdx.x >> 5;
    #pragma unroll
    for (int i = 0; i < 32; i += 8)
        tl[ty + i][tx] = in[(size_t)(r0 + ty + i) * C + c0 + tx];
    __syncthreads();
    #pragma unroll
    for (int i = 0; i < 32; i += 8)
        out[(size_t)(c0 + ty + i) * R + r0 + tx] = __float2half_rn(tl[tx][ty + i]);
}

// ---------------------------------------------------------------------------
// LayerNorm: warp-per-row (8 rows / 256-thread block), shfl-only reduction.
// Writes fp16.
// ---------------------------------------------------------------------------
__global__ __launch_bounds__(256) void layernorm_kernel(
    const float* __restrict__ x, const float* __restrict__ gamma,
    const float* __restrict__ beta, __half* __restrict__ out)
{
    const int warp = threadIdx.x >> 5;
    const int lane = threadIdx.x & 31;
    const int row  = blockIdx.x * 8 + warp;
    const float* xr = x + (size_t)row * DD;

    float4 xv[8];
    float s = 0.f, ss = 0.f;
    #pragma unroll
    for (int i = 0; i < 8; i++) {
        xv[i] = *(const float4*)(xr + i * 128 + lane * 4);
        s  += xv[i].x + xv[i].y + xv[i].z + xv[i].w;
        ss += xv[i].x * xv[i].x + xv[i].y * xv[i].y +
              xv[i].z * xv[i].z + xv[i].w * xv[i].w;
    }
    #pragma unroll
    for (int o = 16; o > 0; o >>= 1) {
        s  += __shfl_xor_sync(0xffffffffu, s, o);
        ss += __shfl_xor_sync(0xffffffffu, ss, o);
    }
    const float mean = s * (1.0f / DD);
    const float var  = ss * (1.0f / DD) - mean * mean;
    const float inv  = rsqrtf(var + EPS);

    __half* orow = out + (size_t)row * DD;
    #pragma unroll
    for (int i = 0; i < 8; i++) {
        const int c = i * 128 + lane * 4;
        float4 gv = *(const float4*)(gamma + c);
        float4 bv = *(const float4*)(beta + c);
        __half2 a = __floats2half2_rn(gv.x * (xv[i].x - mean) * inv + bv.x,
                                      gv.y * (xv[i].y - mean) * inv + bv.y);
        __half2 b = __floats2half2_rn(gv.z * (xv[i].z - mean) * inv + bv.z,
                                      gv.w * (xv[i].w - mean) * inv + bv.w);
        uint2 u;
        u.x = *(uint32_t*)&a;
        u.y = *(uint32_t*)&b;
        *(uint2*)(orow + c) = u;
    }
}

// ---------------------------------------------------------------------------
// GELU (tanh approximation, matches reference)
// ---------------------------------------------------------------------------
__device__ __forceinline__ float gelu_f(float x)
{
    const float c = 0.7978845608028654f;  // sqrt(2/pi)
    float inner = c * (x + 0.044715f * x * x * x);
    return 0.5f * x * (1.0f + tanhf(inner));
}

// ---------------------------------------------------------------------------
// fp16 tensor-core GEMM:  C[M,N] = A[M,K] @ Bt[N,K]^T  (+bias)(+gelu)(+resid)
// CTA tile 128x256, BK=64, 512 threads / 16 warps, warp tile 32x64,
// m16n8k16, ldmatrix fetch, cp.async 3-stage. (unchanged from R14)
// ---------------------------------------------------------------------------
#define GRSTR 144
#define A_BYTES (128 * GRSTR)       // 18432
#define B_BYTES (256 * GRSTR)       // 36864
#define STG (A_BYTES + B_BYTES)     // 55296
#define NSF 3
#define GEMM_SMEM (NSF * STG)       // 165888

__global__ __launch_bounds__(512, 1) void gemm_h(
    const __half* __restrict__ A, const __half* __restrict__ Bt,
    const float* __restrict__ bias,   // may be null
    const float* __restrict__ resid,  // may be null
    void* __restrict__ Cout,
    int Ndim, int Kdim, int mode)
{
    extern __shared__ __align__(16) char smg[];
    const uint32_t sbase = smem_u32(smg);
    const int tid  = threadIdx.x;
    const int lane = tid & 31;
    const int warp = tid >> 5;      // 0..15
    const int wm   = warp >> 2;     // 0..3
    const int wn   = warp & 3;      // 0..3
    const int gid  = lane >> 2;     // 0..7
    const int tg   = lane & 3;      // 0..3
    const int m0 = blockIdx.y * 128;
    const int n0 = blockIdx.x * 256;

    const uint32_t aoff = (uint32_t)(wm * 32 + (lane & 15)) * GRSTR +
                          (lane >> 4) * 16;
    const uint32_t boff = A_BYTES +
        (uint32_t)(wn * 64 + (lane & 7) + (lane >> 4) * 8) * GRSTR +
        ((lane >> 3) & 1) * 16;

    float acc[2][8][4];
    #pragma unroll
    for (int mt = 0; mt < 2; mt++)
        #pragma unroll
        for (int nt = 0; nt < 8; nt++)
            #pragma unroll
            for (int r = 0; r < 4; r++) acc[mt][nt][r] = 0.f;

    const int nkb = Kdim / 64;

    auto issue = [&](int kb, int slot) {
        const uint32_t sb = sbase + slot * STG;
        #pragma unroll
        for (int p = 0; p < 2; p++) {
            const int id = tid + 512 * p;
            const int row = id >> 3, cc = id & 7;
            cp_async16(sb + row * GRSTR + cc * 16,
                       A + (size_t)(m0 + row) * Kdim + kb * 64 + cc * 8);
        }
        #pragma unroll
        for (int p = 0; p < 4; p++) {
            const int id = tid + 512 * p;
            const int row = id >> 3, cc = id & 7;
            cp_async16(sb + A_BYTES + row * GRSTR + cc * 16,
                       Bt + (size_t)(n0 + row) * Kdim + kb * 64 + cc * 8);
        }
    };

    issue(0, 0); cp_commit();
    issue(1, 1); cp_commit();

    int s_cur = 0, s_nxt = 2;

    for (int kb = 0; kb < nkb; kb++) {
        cp_wait<1>();
        __syncthreads();
        if (kb + 2 < nkb) issue(kb + 2, s_nxt);
        cp_commit();

        const uint32_t sA = sbase + s_cur * STG + aoff;
        const uint32_t sB = sbase + s_cur * STG + boff;

        #pragma unroll
        for (int ks = 0; ks < 4; ks++) {
            uint32_t af[2][4], bf[8][2];
            #pragma unroll
            for (int mt = 0; mt < 2; mt++)
                ldsm_x4(af[mt], sA + mt * (16 * GRSTR) + ks * 32);
            #pragma unroll
            for (int ntp = 0; ntp < 4; ntp++) {
                uint32_t t[4];
                ldsm_x4(t, sB + ntp * (16 * GRSTR) + ks * 32);
                bf[2 * ntp][0] = t[0]; bf[2 * ntp][1] = t[1];
                bf[2 * ntp + 1][0] = t[2]; bf[2 * ntp + 1][1] = t[3];
            }
            #pragma unroll
            for (int mt = 0; mt < 2; mt++)
                #pragma unroll
                for (int nt = 0; nt < 8; nt++)
                    mma_f16(acc[mt][nt], af[mt], bf[nt]);
        }

        s_cur = s_cur + 1 == NSF ? 0 : s_cur + 1;
        s_nxt = s_nxt + 1 == NSF ? 0 : s_nxt + 1;
    }

    #pragma unroll
    for (int mt = 0; mt < 2; mt++) {
        #pragma unroll
        for (int half = 0; half < 2; half++) {
            const int row = m0 + wm * 32 + mt * 16 + gid + half * 8;
            #pragma unroll
            for (int nt = 0; nt < 8; nt++) {
                const int col = n0 + wn * 64 + nt * 8 + 2 * tg;
                float v0 = acc[mt][nt][half * 2 + 0];
                float v1 = acc[mt][nt][half * 2 + 1];
                if (bias) { v0 += bias[col]; v1 += bias[col + 1]; }
                if (mode == 1) {
                    __half2 h2 = __floats2half2_rn(gelu_f(v0), gelu_f(v1));
                    *(__half2*)((__half*)Cout + (size_t)row * Ndim + col) = h2;
                } else if (mode == 3) {
                    __half2 h2 = __floats2half2_rn(v0, v1);
                    *(__half2*)((__half*)Cout + (size_t)row * Ndim + col) = h2;
                } else {
                    if (resid) {
                        const float* Rr = resid + (size_t)row * Ndim;
                        v0 += Rr[col]; v1 += Rr[col + 1];
                    }
                    float2 o; o.x = v0; o.y = v1;
                    *(float2*)((float*)Cout + (size_t)row * Ndim + col) = o;
                }
            }
        }
    }
}

// ---------------------------------------------------------------------------
// fp16 tensor-core causal flash attention, PAIRED q-tiles.
// One 256-thread CTA = two warp-groups, handling q-tiles (2p, 2p+1) and
// sharing the K/V smem stream (halves K/V loads + sync overhead per work).
// P in registers, exp2-domain softmax, K/V double buffered.
// smem: Q0, Q1, K0, V0, K1, V1 = 6 x 9216 = 54 KB. 2 CTAs/SM (regs).
// ---------------------------------------------------------------------------
#define AQSTR (3 * DD)
#define ARSTR 144                   // bytes per smem row
#define ATILE_B (64 * ARSTR)        // 9216
#define ATTN_SMEM (6 * ATILE_B)     // 55296

__global__ __launch_bounds__(256, 2) void attn_h(
    const __half* __restrict__ qkv, __half* __restrict__ out)
{
    extern __shared__ __align__(16) char sma[];
    const uint32_t sb = smem_u32(sma);
    // layout: Q(wg=0), Q(wg=1), K0, V0, K1, V1

    const int tid  = threadIdx.x;
    const int lane = tid & 31;
    const int warp = tid >> 5;      // 0..7
    const int wg   = warp >> 2;     // warp-group: 0 or 1
    const int wq   = warp & 3;      // warp within group
    const int gid  = lane >> 2;
    const int tg   = lane & 3;
    const int bh = blockIdx.y;
    const int b  = bh / HH;
    const int h  = bh % HH;
    const int pt = gridDim.x - 1 - blockIdx.x;   // heavy pairs first
    const int qg = 2 * pt + wg;                  // this group's q-tile
    const int q0 = qg * 64;
    const int ktmax = 2 * pt + 1;                // loop bound (pair max)

    const size_t qbase = ((size_t)b * TT) * AQSTR + (size_t)h * HD;
    const size_t obase = ((size_t)b * TT) * DD + (size_t)h * HD;

    auto issue_kv = [&](int kt_i, int buf) {
        const int k0i = kt_i * 64;
        const uint32_t Kb = sb + (2 + 2 * buf) * ATILE_B;
        const uint32_t Vb = sb + (3 + 2 * buf) * ATILE_B;
        const __half* ksrc = qkv + qbase + DD     + (size_t)k0i * AQSTR;
        const __half* vsrc = qkv + qbase + 2 * DD + (size_t)k0i * AQSTR;
        #pragma unroll
        for (int p = 0; p < 2; p++) {
            const int id = tid + 256 * p;
            const int r = id >> 3, c = id & 7;
            cp_async16(Kb + r * ARSTR + c * 16, ksrc + (size_t)r * AQSTR + c * 8);
        }
        #pragma unroll
        for (int p = 0; p < 2; p++) {
            const int id = tid + 256 * p;
            const int r = id >> 3, c = id & 7;
            cp_async16(Vb + r * ARSTR + c * 16, vsrc + (size_t)r * AQSTR + c * 8);
        }
    };

    // prologue: both Q tiles (1024 chunks over 256 threads) + KV(0)
    {
        #pragma unroll
        for (int p = 0; p < 4; p++) {
            const int id = tid + 256 * p;
            const int tile = id >> 9;          // 0 or 1
            const int idx = id & 511;
            const int r = idx >> 3, c = idx & 7;
            const __half* src = qkv + qbase + (size_t)((2 * pt + tile) * 64) * AQSTR;
            cp_async16(sb + tile * ATILE_B + r * ARSTR + c * 16,
                       src + (size_t)r * AQSTR + c * 8);
        }
        cp_commit();
    }
    issue_kv(0, 0);
    cp_commit();

    float mrow[2] = {-1e30f, -1e30f};
    float lrow[2] = {0.f, 0.f};
    float o[8][4];
    #pragma unroll
    for (int nf = 0; nf < 8; nf++)
        #pragma unroll
        for (int c = 0; c < 4; c++) o[nf][c] = 0.f;

    const uint32_t Qb = sb + wg * ATILE_B;
    const uint32_t qp_off = (uint32_t)(wq * 16 + (lane & 15)) * ARSTR +
                            (lane >> 4) * 16;
    const uint32_t kp_off = (uint32_t)((lane & 7) + (lane >> 4) * 8) * ARSTR +
                            ((lane >> 3) & 1) * 16;
    const uint32_t vp_off = (uint32_t)((lane & 7) + ((lane >> 3) & 1) * 8) * ARSTR +
                            (lane >> 4) * 16;

    const float SC2 = 0.125f * 1.4426950408889634f;

    for (int kt = 0; kt <= ktmax; kt++) {
        const int cur = kt & 1;
        __syncthreads();
        if (kt < ktmax) {
            issue_kv(kt + 1, cur ^ 1);
            cp_commit();
            cp_wait<1>();
        } else {
            cp_wait<0>();
        }
        __syncthreads();

        if (kt > qg) continue;   // group 0 idle on the pair's last iteration

        const uint32_t Kc = sb + (2 + 2 * cur) * ATILE_B;
        const uint32_t Vc = sb + (3 + 2 * cur) * ATILE_B;

        // S = Q K^T  (warp: 16 x 64)
        float s[8][4];
        #pragma unroll
        for (int nf = 0; nf < 8; nf++)
            #pragma unroll
            for (int c = 0; c < 4; c++) s[nf][c] = 0.f;
        #pragma unroll
        for (int ks = 0; ks < 4; ks++) {
            uint32_t aq[4];
            ldsm_x4(aq, Qb + qp_off + ks * 32);
            #pragma unroll
            for (int ntp = 0; ntp < 4; ntp++) {
                uint32_t t[4];
                ldsm_x4(t, Kc + kp_off + ntp * 16 * ARSTR + ks * 32);
                uint32_t b0[2] = {t[0], t[1]};
                uint32_t b1[2] = {t[2], t[3]};
                mma_f16(s[2 * ntp],     aq, b0);
                mma_f16(s[2 * ntp + 1], aq, b1);
            }
        }

        const bool diag = (kt == qg);
        #pragma unroll
        for (int nf = 0; nf < 8; nf++) {
            #pragma unroll
            for (int c = 0; c < 4; c++) {
                float val = s[nf][c] * SC2;
                if (diag) {
                    int row = wq * 16 + gid + (c >= 2 ? 8 : 0);
                    int col = nf * 8 + 2 * tg + (c & 1);
                    if (col > row) val = -1e30f;
                }
                s[nf][c] = val;
            }
        }

        float mx0 = -1e30f, mx1 = -1e30f;
        #pragma unroll
        for (int nf = 0; nf < 8; nf++) {
            mx0 = fmaxf(mx0, fmaxf(s[nf][0], s[nf][1]));
            mx1 = fmaxf(mx1, fmaxf(s[nf][2], s[nf][3]));
        }
        #pragma unroll
        for (int w = 1; w <= 2; w <<= 1) {
            mx0 = fmaxf(mx0, __shfl_xor_sync(0xffffffffu, mx0, w));
            mx1 = fmaxf(mx1, __shfl_xor_sync(0xffffffffu, mx1, w));
        }
        float mn0 = fmaxf(mrow[0], mx0);
        float mn1 = fmaxf(mrow[1], mx1);
        float al0 = exp2f(mrow[0] - mn0);
        float al1 = exp2f(mrow[1] - mn1);

        float sum0 = 0.f, sum1 = 0.f;
        #pragma unroll
        for (int nf = 0; nf < 8; nf++) {
            s[nf][0] = exp2f(s[nf][0] - mn0);
            s[nf][1] = exp2f(s[nf][1] - mn0);
            s[nf][2] = exp2f(s[nf][2] - mn1);
            s[nf][3] = exp2f(s[nf][3] - mn1);
            sum0 += s[nf][0] + s[nf][1];
            sum1 += s[nf][2] + s[nf][3];
        }
        #pragma unroll
        for (int w = 1; w <= 2; w <<= 1) {
            sum0 += __shfl_xor_sync(0xffffffffu, sum0, w);
            sum1 += __shfl_xor_sync(0xffffffffu, sum1, w);
        }
        lrow[0] = lrow[0] * al0 + sum0;
        lrow[1] = lrow[1] * al1 + sum1;
        mrow[0] = mn0;
        mrow[1] = mn1;

        #pragma unroll
        for (int nf = 0; nf < 8; nf++) {
            o[nf][0] *= al0; o[nf][1] *= al0;
            o[nf][2] *= al1; o[nf][3] *= al1;
        }

        #pragma unroll
        for (int ks = 0; ks < 4; ks++) {
            uint32_t ap[4];
            ap[0] = pack_h2(s[2 * ks][0],     s[2 * ks][1]);
            ap[1] = pack_h2(s[2 * ks][2],     s[2 * ks][3]);
            ap[2] = pack_h2(s[2 * ks + 1][0], s[2 * ks + 1][1]);
            ap[3] = pack_h2(s[2 * ks + 1][2], s[2 * ks + 1][3]);
            #pragma unroll
            for (int ntp = 0; ntp < 4; ntp++) {
                uint32_t t[4];
                ldsm_x4_t(t, Vc + vp_off + ks * 16 * ARSTR + ntp * 32);
                uint32_t b0[2] = {t[0], t[1]};
                uint32_t b1[2] = {t[2], t[3]};
                mma_f16(o[2 * ntp],     ap, b0);
                mma_f16(o[2 * ntp + 1], ap, b1);
            }
        }
    }

    const float inv0 = 1.0f / lrow[0];
    const float inv1 = 1.0f / lrow[1];
    const int r0 = q0 + wq * 16 + gid;
    #pragma unroll
    for (int nf = 0; nf < 8; nf++) {
        const int col = nf * 8 + 2 * tg;
        __half2 w0 = __floats2half2_rn(o[nf][0] * inv0, o[nf][1] * inv0);
        __half2 w1 = __floats2half2_rn(o[nf][2] * inv1, o[nf][3] * inv1);
        *(__half2*)(out + obase + (size_t)r0 * DD + col)       = w0;
        *(__half2*)(out + obase + (size_t)(r0 + 8) * DD + col) = w1;
    }
}

// ---------------------------------------------------------------------------
// Host launch
// ---------------------------------------------------------------------------
extern "C" void kernel_launch(void* const* d_in, const int* in_sizes, int n_in,
                              void* d_out, int out_size)
{
    const float* x    = (const float*)d_in[0];
    const float* Wq   = (const float*)d_in[1];
    const float* Wk   = (const float*)d_in[2];
    const float* Wv   = (const float*)d_in[3];
    const float* Wo   = (const float*)d_in[4];
    const float* bo   = (const float*)d_in[5];
    const float* W1   = (const float*)d_in[6];
    const float* b1   = (const float*)d_in[7];
    const float* W2   = (const float*)d_in[8];
    const float* b2   = (const float*)d_in[9];
    const float* g1   = (const float*)d_in[10];
    const float* be1  = (const float*)d_in[11];
    const float* g2   = (const float*)d_in[12];
    const float* be2  = (const float*)d_in[13];
    float* out = (float*)d_out;

    __half *h, *qkv, *attn, *h2, *ff1, *wqkv, *wo, *w1, *w2;
    float *x2;
    cudaGetSymbolAddress((void**)&h,    g_h);
    cudaGetSymbolAddress((void**)&qkv,  g_qkv);
    cudaGetSymbolAddress((void**)&attn, g_attn);
    cudaGetSymbolAddress((void**)&x2,   g_x2);
    cudaGetSymbolAddress((void**)&h2,   g_h2);
    cudaGetSymbolAddress((void**)&ff1,  g_ff1);
    cudaGetSymbolAddress((void**)&wqkv, g_wqkv);
    cudaGetSymbolAddress((void**)&wo,   g_wo);
    cudaGetSymbolAddress((void**)&w1,   g_w1);
    cudaGetSymbolAddress((void**)&w2,   g_w2);

    cudaFuncSetAttribute(attn_h,
                         cudaFuncAttributeMaxDynamicSharedMemorySize, ATTN_SMEM);
    cudaFuncSetAttribute(gemm_h,
                         cudaFuncAttributeMaxDynamicSharedMemorySize, GEMM_SMEM);

    // 0) weight preprocessing: all transposes in one launch
    transpose_all_kernel<<<12288, 256>>>(Wq, Wk, Wv, Wo, W1, W2,
                                         wqkv, wo, w1, w2);

    // 1) LN1 -> fp16 (warp-per-row)
    layernorm_kernel<<<MM / 8, 256>>>(x, g1, be1, h);

    // 2) fused QKV projection -> fp16
    gemm_h<<<dim3(3 * DD / 256, MM / 128), 512, GEMM_SMEM>>>(
        h, wqkv, nullptr, nullptr, qkv, 3 * DD, DD, 3);

    // 3) causal attention (fp16 tensor cores, paired q-tiles)
    attn_h<<<dim3(TT / 128, BB * HH), 256, ATTN_SMEM>>>(qkv, attn);

    // 4) output projection + bias + residual(x) -> fp32
    dim3 gDD(DD / 256, MM / 128);
    gemm_h<<<gDD, 512, GEMM_SMEM>>>(attn, wo, bo, x, x2, DD, DD, 2);

    // 5) LN2 -> fp16 (warp-per-row)
    layernorm_kernel<<<MM / 8, 256>>>(x2, g2, be2, h2);

    // 6) FFN1 + bias + GELU -> fp16
    gemm_h<<<dim3(FF / 256, MM / 128), 512, GEMM_SMEM>>>(
        h2, w1, b1, nullptr, ff1, FF, DD, 1);

    // 7) FFN2 + bias + residual(x2) -> out (fp32)
    gemm_h<<<gDD, 512, GEMM_SMEM>>>(ff1, w2, b2, x2, out, DD, FF, 2);
}

// round 16
// speedup vs baseline: 1.0904x; 1.0904x over previous
#include <cuda_runtime.h>
#include <cuda_fp16.h>
#include <math.h>
#include <stdint.h>

// ---------------------------------------------------------------------------
// Problem constants
// ---------------------------------------------------------------------------
#define BB 4
#define TT 2048
#define DD 1024
#define HH 16
#define HD 64
#define FF 4096
#define MM (BB * TT)       // 8192 rows
#define EPS 1e-5f

// ---------------------------------------------------------------------------
// Scratch (allocation-free: __device__ globals)
// ---------------------------------------------------------------------------
__device__ __half g_h   [(size_t)MM * DD];      // LN1 out (fp16)
__device__ __half g_qkv [(size_t)MM * 3 * DD];  // QKV out (fp16)
__device__ __half g_attn[(size_t)MM * DD];      // attention out (fp16)
__device__ float  g_x2  [(size_t)MM * DD];      // residual stream 2 (fp32)
__device__ __half g_h2  [(size_t)MM * DD];      // LN2 out (fp16)
__device__ __half g_ff1 [(size_t)MM * FF];      // FFN1 out (fp16)
// fp16 weights, transposed to [N][K]
__device__ __half g_wqkv[(size_t)(3 * DD) * DD];
__device__ __half g_wo  [(size_t)DD * DD];
__device__ __half g_w1  [(size_t)FF * DD];
__device__ __half g_w2  [(size_t)DD * FF];

// ---------------------------------------------------------------------------
// helpers
// ---------------------------------------------------------------------------
__device__ __forceinline__ void mma_f16(float c[4], const uint32_t a[4],
                                        const uint32_t b[2]) {
    asm volatile(
        "mma.sync.aligned.m16n8k16.row.col.f32.f16.f16.f32 "
        "{%0,%1,%2,%3}, {%4,%5,%6,%7}, {%8,%9}, {%0,%1,%2,%3};"
        : "+f"(c[0]), "+f"(c[1]), "+f"(c[2]), "+f"(c[3])
        : "r"(a[0]), "r"(a[1]), "r"(a[2]), "r"(a[3]), "r"(b[0]), "r"(b[1]));
}
__device__ __forceinline__ void ldsm_x4(uint32_t r[4], uint32_t saddr) {
    asm volatile("ldmatrix.sync.aligned.m8n8.x4.shared.b16 {%0,%1,%2,%3}, [%4];"
        : "=r"(r[0]), "=r"(r[1]), "=r"(r[2]), "=r"(r[3]) : "r"(saddr));
}
__device__ __forceinline__ void ldsm_x4_t(uint32_t r[4], uint32_t saddr) {
    asm volatile("ldmatrix.sync.aligned.m8n8.x4.trans.shared.b16 {%0,%1,%2,%3}, [%4];"
        : "=r"(r[0]), "=r"(r[1]), "=r"(r[2]), "=r"(r[3]) : "r"(saddr));
}
__device__ __forceinline__ void cp_async16(uint32_t saddr, const void* gptr) {
    asm volatile("cp.async.cg.shared.global [%0], [%1], 16;"
                 :: "r"(saddr), "l"(gptr) : "memory");
}
__device__ __forceinline__ void cp_commit() {
    asm volatile("cp.async.commit_group;" ::: "memory");
}
template <int N>
__device__ __forceinline__ void cp_wait() {
    asm volatile("cp.async.wait_group %0;" :: "n"(N) : "memory");
}
__device__ __forceinline__ uint32_t smem_u32(const void* p) {
    uint32_t a;
    asm("{ .reg .u64 t; cvta.to.shared.u64 t, %1; cvt.u32.u64 %0, t; }"
        : "=r"(a) : "l"(p));
    return a;
}
__device__ __forceinline__ uint32_t pack_h2(float a, float b) {
    __half2 h = __floats2half2_rn(a, b);
    return *(uint32_t*)&h;
}

// ---------------------------------------------------------------------------
// Weight preprocessing: all 6 transposes ([R][C] fp32 -> [C][R] fp16) fused
// into one launch.
// ---------------------------------------------------------------------------
__global__ __launch_bounds__(256) void transpose_all_kernel(
    const float* __restrict__ Wq, const float* __restrict__ Wk,
    const float* __restrict__ Wv, const float* __restrict__ Wo,
    const float* __restrict__ W1, const float* __restrict__ W2,
    __half* __restrict__ wqkv, __half* __restrict__ wo,
    __half* __restrict__ w1, __half* __restrict__ w2)
{
    const int id = blockIdx.x;
    const float* in;
    __half* out;
    int R, C, bx, by;
    if (id < 4096) {
        const int w = id >> 10, t = id & 1023;
        bx = t & 31; by = t >> 5;
        R = DD; C = DD;
        if (w == 0)      { in = Wq; out = wqkv; }
        else if (w == 1) { in = Wk; out = wqkv + (size_t)DD * DD; }
        else if (w == 2) { in = Wv; out = wqkv + (size_t)2 * DD * DD; }
        else             { in = Wo; out = wo; }
    } else if (id < 8192) {
        const int t = id - 4096;
        bx = t & 127; by = t >> 7;
        in = W1; out = w1; R = DD; C = FF;
    } else {
        const int t = id - 8192;
        bx = t & 31; by = t >> 5;
        in = W2; out = w2; R = FF; C = DD;
    }

    __shared__ float tl[32][33];
    const int c0 = bx * 32;
    const int r0 = by * 32;
    const int tx = threadIdx.x & 31, ty = threadIdx.x >> 5;
    #pragma unroll
    for (int i = 0; i < 32; i += 8)
        tl[ty + i][tx] = in[(size_t)(r0 + ty + i) * C + c0 + tx];
    __syncthreads();
    #pragma unroll
    for (int i = 0; i < 32; i += 8)
        out[(size_t)(c0 + ty + i) * R + r0 + tx] = __float2half_rn(tl[tx][ty + i]);
}

// ---------------------------------------------------------------------------
// LayerNorm: warp-per-row (8 rows / 256-thread block), shfl-only reduction.
// ---------------------------------------------------------------------------
__global__ __launch_bounds__(256) void layernorm_kernel(
    const float* __restrict__ x, const float* __restrict__ gamma,
    const float* __restrict__ beta, __half* __restrict__ out)
{
    const int warp = threadIdx.x >> 5;
    const int lane = threadIdx.x & 31;
    const int row  = blockIdx.x * 8 + warp;
    const float* xr = x + (size_t)row * DD;

    float4 xv[8];
    float s = 0.f, ss = 0.f;
    #pragma unroll
    for (int i = 0; i < 8; i++) {
        xv[i] = *(const float4*)(xr + i * 128 + lane * 4);
        s  += xv[i].x + xv[i].y + xv[i].z + xv[i].w;
        ss += xv[i].x * xv[i].x + xv[i].y * xv[i].y +
              xv[i].z * xv[i].z + xv[i].w * xv[i].w;
    }
    #pragma unroll
    for (int o = 16; o > 0; o >>= 1) {
        s  += __shfl_xor_sync(0xffffffffu, s, o);
        ss += __shfl_xor_sync(0xffffffffu, ss, o);
    }
    const float mean = s * (1.0f / DD);
    const float var  = ss * (1.0f / DD) - mean * mean;
    const float inv  = rsqrtf(var + EPS);

    __half* orow = out + (size_t)row * DD;
    #pragma unroll
    for (int i = 0; i < 8; i++) {
        const int c = i * 128 + lane * 4;
        float4 gv = *(const float4*)(gamma + c);
        float4 bv = *(const float4*)(beta + c);
        __half2 a = __floats2half2_rn(gv.x * (xv[i].x - mean) * inv + bv.x,
                                      gv.y * (xv[i].y - mean) * inv + bv.y);
        __half2 b = __floats2half2_rn(gv.z * (xv[i].z - mean) * inv + bv.z,
                                      gv.w * (xv[i].w - mean) * inv + bv.w);
        uint2 u;
        u.x = *(uint32_t*)&a;
        u.y = *(uint32_t*)&b;
        *(uint2*)(orow + c) = u;
    }
}

// ---------------------------------------------------------------------------
// GELU (tanh approximation, matches reference)
// ---------------------------------------------------------------------------
__device__ __forceinline__ float gelu_f(float x)
{
    const float c = 0.7978845608028654f;  // sqrt(2/pi)
    float inner = c * (x + 0.044715f * x * x * x);
    return 0.5f * x * (1.0f + tanhf(inner));
}

// ---------------------------------------------------------------------------
// fp16 tensor-core GEMM:  C[M,N] = A[M,K] @ Bt[N,K]^T  (+bias)(+gelu)(+resid)
// CTA tile 128x128, BK=64, 256 threads / 8 warps (4x2), warp tile 32x64,
// m16n8k16, ldmatrix fetch, cp.async 3-stage. 108 KB smem -> 2 CTAs/SM:
// two independent pipelines per SM hide each other's barrier/wait stalls.
// mode: 0 = fp32 out plain, 1 = fp16 out bias+gelu, 2 = fp32 out bias+resid,
//       3 = fp16 out plain
// ---------------------------------------------------------------------------
#define GRSTR 144
#define A_BYTES (128 * GRSTR)       // 18432
#define B_BYTES (128 * GRSTR)       // 18432
#define STG (A_BYTES + B_BYTES)     // 36864
#define NSF 3
#define GEMM_SMEM (NSF * STG)       // 110592

__global__ __launch_bounds__(256, 2) void gemm_h(
    const __half* __restrict__ A, const __half* __restrict__ Bt,
    const float* __restrict__ bias,   // may be null
    const float* __restrict__ resid,  // may be null
    void* __restrict__ Cout,
    int Ndim, int Kdim, int mode)
{
    extern __shared__ __align__(16) char smg[];
    const uint32_t sbase = smem_u32(smg);
    const int tid  = threadIdx.x;
    const int lane = tid & 31;
    const int warp = tid >> 5;      // 0..7
    const int wm   = warp >> 1;     // 0..3  (32-row slab)
    const int wn   = warp & 1;      // 0..1  (64-col slab)
    const int gid  = lane >> 2;     // 0..7
    const int tg   = lane & 3;      // 0..3
    const int m0 = blockIdx.y * 128;
    const int n0 = blockIdx.x * 128;

    const uint32_t aoff = (uint32_t)(wm * 32 + (lane & 15)) * GRSTR +
                          (lane >> 4) * 16;
    const uint32_t boff = A_BYTES +
        (uint32_t)(wn * 64 + (lane & 7) + (lane >> 4) * 8) * GRSTR +
        ((lane >> 3) & 1) * 16;

    float acc[2][8][4];
    #pragma unroll
    for (int mt = 0; mt < 2; mt++)
        #pragma unroll
        for (int nt = 0; nt < 8; nt++)
            #pragma unroll
            for (int r = 0; r < 4; r++) acc[mt][nt][r] = 0.f;

    const int nkb = Kdim / 64;

    auto issue = [&](int kb, int slot) {
        const uint32_t sb = sbase + slot * STG;
        #pragma unroll
        for (int p = 0; p < 4; p++) {   // A: 1024 chunks of 16B
            const int id = tid + 256 * p;
            const int row = id >> 3, cc = id & 7;
            cp_async16(sb + row * GRSTR + cc * 16,
                       A + (size_t)(m0 + row) * Kdim + kb * 64 + cc * 8);
        }
        #pragma unroll
        for (int p = 0; p < 4; p++) {   // B: 1024 chunks
            const int id = tid + 256 * p;
            const int row = id >> 3, cc = id & 7;
            cp_async16(sb + A_BYTES + row * GRSTR + cc * 16,
                       Bt + (size_t)(n0 + row) * Kdim + kb * 64 + cc * 8);
        }
    };

    issue(0, 0); cp_commit();
    issue(1, 1); cp_commit();

    int s_cur = 0, s_nxt = 2;

    for (int kb = 0; kb < nkb; kb++) {
        cp_wait<1>();
        __syncthreads();
        if (kb + 2 < nkb) issue(kb + 2, s_nxt);
        cp_commit();

        const uint32_t sA = sbase + s_cur * STG + aoff;
        const uint32_t sB = sbase + s_cur * STG + boff;

        #pragma unroll
        for (int ks = 0; ks < 4; ks++) {
            uint32_t af[2][4], bf[8][2];
            #pragma unroll
            for (int mt = 0; mt < 2; mt++)
                ldsm_x4(af[mt], sA + mt * (16 * GRSTR) + ks * 32);
            #pragma unroll
            for (int ntp = 0; ntp < 4; ntp++) {
                uint32_t t[4];
                ldsm_x4(t, sB + ntp * (16 * GRSTR) + ks * 32);
                bf[2 * ntp][0] = t[0]; bf[2 * ntp][1] = t[1];
                bf[2 * ntp + 1][0] = t[2]; bf[2 * ntp + 1][1] = t[3];
            }
            #pragma unroll
            for (int mt = 0; mt < 2; mt++)
                #pragma unroll
                for (int nt = 0; nt < 8; nt++)
                    mma_f16(acc[mt][nt], af[mt], bf[nt]);
        }

        s_cur = s_cur + 1 == NSF ? 0 : s_cur + 1;
        s_nxt = s_nxt + 1 == NSF ? 0 : s_nxt + 1;
    }

    #pragma unroll
    for (int mt = 0; mt < 2; mt++) {
        #pragma unroll
        for (int half = 0; half < 2; half++) {
            const int row = m0 + wm * 32 + mt * 16 + gid + half * 8;
            #pragma unroll
            for (int nt = 0; nt < 8; nt++) {
                const int col = n0 + wn * 64 + nt * 8 + 2 * tg;
                float v0 = acc[mt][nt][half * 2 + 0];
                float v1 = acc[mt][nt][half * 2 + 1];
                if (bias) { v0 += bias[col]; v1 += bias[col + 1]; }
                if (mode == 1) {
                    __half2 h2 = __floats2half2_rn(gelu_f(v0), gelu_f(v1));
                    *(__half2*)((__half*)Cout + (size_t)row * Ndim + col) = h2;
                } else if (mode == 3) {
                    __half2 h2 = __floats2half2_rn(v0, v1);
                    *(__half2*)((__half*)Cout + (size_t)row * Ndim + col) = h2;
                } else {
                    if (resid) {
                        const float* Rr = resid + (size_t)row * Ndim;
                        v0 += Rr[col]; v1 += Rr[col + 1];
                    }
                    float2 o; o.x = v0; o.y = v1;
                    *(float2*)((float*)Cout + (size_t)row * Ndim + col) = o;
                }
            }
        }
    }
}

// ---------------------------------------------------------------------------
// fp16 tensor-core causal flash attention (m16n8k16, fp32 accum/softmax).
// P in registers, exp2-domain softmax, K/V double buffered. (R14 version)
// ---------------------------------------------------------------------------
#define AQSTR (3 * DD)
#define ARSTR 144                   // bytes per smem row
#define ATILE_B (64 * ARSTR)        // 9216
#define ATTN_SMEM (5 * ATILE_B)     // 46080

__global__ __launch_bounds__(128, 4) void attn_h(
    const __half* __restrict__ qkv, __half* __restrict__ out)
{
    extern __shared__ __align__(16) char sma[];
    const uint32_t sb = smem_u32(sma);
    const uint32_t Qb = sb;

    const int tid  = threadIdx.x;
    const int lane = tid & 31;
    const int warp = tid >> 5;
    const int gid  = lane >> 2;
    const int tg   = lane & 3;
    const int bh = blockIdx.y;
    const int b  = bh / HH;
    const int h  = bh % HH;
    const int qt = gridDim.x - 1 - blockIdx.x;   // heavy tiles first
    const int q0 = qt * 64;

    const size_t qbase = ((size_t)b * TT) * AQSTR + (size_t)h * HD;
    const size_t obase = ((size_t)b * TT) * DD + (size_t)h * HD;

    auto issue_kv = [&](int kt_i, int buf) {
        const int k0i = kt_i * 64;
        const uint32_t Kb = sb + (1 + 2 * buf) * ATILE_B;
        const uint32_t Vb = sb + (2 + 2 * buf) * ATILE_B;
        const __half* ksrc = qkv + qbase + DD     + (size_t)k0i * AQSTR;
        const __half* vsrc = qkv + qbase + 2 * DD + (size_t)k0i * AQSTR;
        #pragma unroll
        for (int p = 0; p < 4; p++) {
            const int id = tid + 128 * p;
            const int r = id >> 3, c = id & 7;
            cp_async16(Kb + r * ARSTR + c * 16, ksrc + (size_t)r * AQSTR + c * 8);
        }
        #pragma unroll
        for (int p = 0; p < 4; p++) {
            const int id = tid + 128 * p;
            const int r = id >> 3, c = id & 7;
            cp_async16(Vb + r * ARSTR + c * 16, vsrc + (size_t)r * AQSTR + c * 8);
        }
    };

    {
        const __half* src = qkv + qbase + (size_t)q0 * AQSTR;
        #pragma unroll
        for (int p = 0; p < 4; p++) {
            const int id = tid + 128 * p;
            const int r = id >> 3, c = id & 7;
            cp_async16(Qb + r * ARSTR + c * 16, src + (size_t)r * AQSTR + c * 8);
        }
        cp_commit();
    }
    issue_kv(0, 0);
    cp_commit();

    float mrow[2] = {-1e30f, -1e30f};
    float lrow[2] = {0.f, 0.f};
    float o[8][4];
    #pragma unroll
    for (int nf = 0; nf < 8; nf++)
        #pragma unroll
        for (int c = 0; c < 4; c++) o[nf][c] = 0.f;

    const uint32_t qp_off = (uint32_t)(warp * 16 + (lane & 15)) * ARSTR +
                            (lane >> 4) * 16;
    const uint32_t kp_off = (uint32_t)((lane & 7) + (lane >> 4) * 8) * ARSTR +
                            ((lane >> 3) & 1) * 16;
    const uint32_t vp_off = (uint32_t)((lane & 7) + ((lane >> 3) & 1) * 8) * ARSTR +
                            (lane >> 4) * 16;

    const float SC2 = 0.125f * 1.4426950408889634f;

    for (int kt = 0; kt <= qt; kt++) {
        const int cur = kt & 1;
        __syncthreads();
        if (kt < qt) {
            issue_kv(kt + 1, cur ^ 1);
            cp_commit();
            cp_wait<1>();
        } else {
            cp_wait<0>();
        }
        __syncthreads();

        const uint32_t Kc = sb + (1 + 2 * cur) * ATILE_B;
        const uint32_t Vc = sb + (2 + 2 * cur) * ATILE_B;

        float s[8][4];
        #pragma unroll
        for (int nf = 0; nf < 8; nf++)
            #pragma unroll
            for (int c = 0; c < 4; c++) s[nf][c] = 0.f;
        #pragma unroll
        for (int ks = 0; ks < 4; ks++) {
            uint32_t aq[4];
            ldsm_x4(aq, Qb + qp_off + ks * 32);
            #pragma unroll
            for (int ntp = 0; ntp < 4; ntp++) {
                uint32_t t[4];
                ldsm_x4(t, Kc + kp_off + ntp * 16 * ARSTR + ks * 32);
                uint32_t b0[2] = {t[0], t[1]};
                uint32_t b1[2] = {t[2], t[3]};
                mma_f16(s[2 * ntp],     aq, b0);
                mma_f16(s[2 * ntp + 1], aq, b1);
            }
        }

        const bool diag = (kt == qt);
        #pragma unroll
        for (int nf = 0; nf < 8; nf++) {
            #pragma unroll
            for (int c = 0; c < 4; c++) {
                float val = s[nf][c] * SC2;
                if (diag) {
                    int row = warp * 16 + gid + (c >= 2 ? 8 : 0);
                    int col = nf * 8 + 2 * tg + (c & 1);
                    if (col > row) val = -1e30f;
                }
                s[nf][c] = val;
            }
        }

        float mx0 = -1e30f, mx1 = -1e30f;
        #pragma unroll
        for (int nf = 0; nf < 8; nf++) {
            mx0 = fmaxf(mx0, fmaxf(s[nf][0], s[nf][1]));
            mx1 = fmaxf(mx1, fmaxf(s[nf][2], s[nf][3]));
        }
        #pragma unroll
        for (int w = 1; w <= 2; w <<= 1) {
            mx0 = fmaxf(mx0, __shfl_xor_sync(0xffffffffu, mx0, w));
            mx1 = fmaxf(mx1, __shfl_xor_sync(0xffffffffu, mx1, w));
        }
        float mn0 = fmaxf(mrow[0], mx0);
        float mn1 = fmaxf(mrow[1], mx1);
        float al0 = exp2f(mrow[0] - mn0);
        float al1 = exp2f(mrow[1] - mn1);

        float sum0 = 0.f, sum1 = 0.f;
        #pragma unroll
        for (int nf = 0; nf < 8; nf++) {
            s[nf][0] = exp2f(s[nf][0] - mn0);
            s[nf][1] = exp2f(s[nf][1] - mn0);
            s[nf][2] = exp2f(s[nf][2] - mn1);
            s[nf][3] = exp2f(s[nf][3] - mn1);
            sum0 += s[nf][0] + s[nf][1];
            sum1 += s[nf][2] + s[nf][3];
        }
        #pragma unroll
        for (int w = 1; w <= 2; w <<= 1) {
            sum0 += __shfl_xor_sync(0xffffffffu, sum0, w);
            sum1 += __shfl_xor_sync(0xffffffffu, sum1, w);
        }
        lrow[0] = lrow[0] * al0 + sum0;
        lrow[1] = lrow[1] * al1 + sum1;
        mrow[0] = mn0;
        mrow[1] = mn1;

        #pragma unroll
        for (int nf = 0; nf < 8; nf++) {
            o[nf][0] *= al0; o[nf][1] *= al0;
            o[nf][2] *= al1; o[nf][3] *= al1;
        }

        #pragma unroll
        for (int ks = 0; ks < 4; ks++) {
            uint32_t ap[4];
            ap[0] = pack_h2(s[2 * ks][0],     s[2 * ks][1]);
            ap[1] = pack_h2(s[2 * ks][2],     s[2 * ks][3]);
            ap[2] = pack_h2(s[2 * ks + 1][0], s[2 * ks + 1][1]);
            ap[3] = pack_h2(s[2 * ks + 1][2], s[2 * ks + 1][3]);
            #pragma unroll
            for (int ntp = 0; ntp < 4; ntp++) {
                uint32_t t[4];
                ldsm_x4_t(t, Vc + vp_off + ks * 16 * ARSTR + ntp * 32);
                uint32_t b0[2] = {t[0], t[1]};
                uint32_t b1[2] = {t[2], t[3]};
                mma_f16(o[2 * ntp],     ap, b0);
                mma_f16(o[2 * ntp + 1], ap, b1);
            }
        }
    }

    const float inv0 = 1.0f / lrow[0];
    const float inv1 = 1.0f / lrow[1];
    const int r0 = q0 + warp * 16 + gid;
    #pragma unroll
    for (int nf = 0; nf < 8; nf++) {
        const int col = nf * 8 + 2 * tg;
        __half2 w0 = __floats2half2_rn(o[nf][0] * inv0, o[nf][1] * inv0);
        __half2 w1 = __floats2half2_rn(o[nf][2] * inv1, o[nf][3] * inv1);
        *(__half2*)(out + obase + (size_t)r0 * DD + col)       = w0;
        *(__half2*)(out + obase + (size_t)(r0 + 8) * DD + col) = w1;
    }
}

// ---------------------------------------------------------------------------
// Host launch
// ---------------------------------------------------------------------------
extern "C" void kernel_launch(void* const* d_in, const int* in_sizes, int n_in,
                              void* d_out, int out_size)
{
    const float* x    = (const float*)d_in[0];
    const float* Wq   = (const float*)d_in[1];
    const float* Wk   = (const float*)d_in[2];
    const float* Wv   = (const float*)d_in[3];
    const float* Wo   = (const float*)d_in[4];
    const float* bo   = (const float*)d_in[5];
    const float* W1   = (const float*)d_in[6];
    const float* b1   = (const float*)d_in[7];
    const float* W2   = (const float*)d_in[8];
    const float* b2   = (const float*)d_in[9];
    const float* g1   = (const float*)d_in[10];
    const float* be1  = (const float*)d_in[11];
    const float* g2   = (const float*)d_in[12];
    const float* be2  = (const float*)d_in[13];
    float* out = (float*)d_out;

    __half *h, *qkv, *attn, *h2, *ff1, *wqkv, *wo, *w1, *w2;
    float *x2;
    cudaGetSymbolAddress((void**)&h,    g_h);
    cudaGetSymbolAddress((void**)&qkv,  g_qkv);
    cudaGetSymbolAddress((void**)&attn, g_attn);
    cudaGetSymbolAddress((void**)&x2,   g_x2);
    cudaGetSymbolAddress((void**)&h2,   g_h2);
    cudaGetSymbolAddress((void**)&ff1,  g_ff1);
    cudaGetSymbolAddress((void**)&wqkv, g_wqkv);
    cudaGetSymbolAddress((void**)&wo,   g_wo);
    cudaGetSymbolAddress((void**)&w1,   g_w1);
    cudaGetSymbolAddress((void**)&w2,   g_w2);

    cudaFuncSetAttribute(attn_h,
                         cudaFuncAttributeMaxDynamicSharedMemorySize, ATTN_SMEM);
    cudaFuncSetAttribute(gemm_h,
                         cudaFuncAttributeMaxDynamicSharedMemorySize, GEMM_SMEM);

    // 0) weight preprocessing: all transposes in one launch
    transpose_all_kernel<<<12288, 256>>>(Wq, Wk, Wv, Wo, W1, W2,
                                         wqkv, wo, w1, w2);

    // 1) LN1 -> fp16 (warp-per-row)
    layernorm_kernel<<<MM / 8, 256>>>(x, g1, be1, h);

    // 2) fused QKV projection -> fp16
    gemm_h<<<dim3(3 * DD / 128, MM / 128), 256, GEMM_SMEM>>>(
        h, wqkv, nullptr, nullptr, qkv, 3 * DD, DD, 3);

    // 3) causal attention (fp16 tensor cores)
    attn_h<<<dim3(TT / 64, BB * HH), 128, ATTN_SMEM>>>(qkv, attn);

    // 4) output projection + bias + residual(x) -> fp32
    dim3 gDD(DD / 128, MM / 128);
    gemm_h<<<gDD, 256, GEMM_SMEM>>>(attn, wo, bo, x, x2, DD, DD, 2);

    // 5) LN2 -> fp16 (warp-per-row)
    layernorm_kernel<<<MM / 8, 256>>>(x2, g2, be2, h2);

    // 6) FFN1 + bias + GELU -> fp16
    gemm_h<<<dim3(FF / 128, MM / 128), 256, GEMM_SMEM>>>(
        h2, w1, b1, nullptr, ff1, FF, DD, 1);

    // 7) FFN2 + bias + residual(x2) -> out (fp32)
    gemm_h<<<gDD, 256, GEMM_SMEM>>>(ff1, w2, b2, x2, out, DD, FF, 2);
}